// round 5
// baseline (speedup 1.0000x reference)
#include <cuda_runtime.h>
#include <cuda_bf16.h>
#include <cstdint>

// Problem constants
#define B_    32
#define CIN   256
#define HIN   64
#define WIN   64
#define COUT  32
#define KH    9
#define KW    9
#define OH    28
#define OW    28
#define T_    8
#define NPOS  (COUT*OH*OW)   // 25088

// Conv-kernel tiling: 4 output rows per block, ic split into 2 halves.
#define THA    4
#define XROWSA (2*(THA-1)+KH)   // 15 input rows
#define NICH   (CIN/2)          // 128 ic per half
#define NTHR_A 128              // 16 spatial groups x 8 oc groups

// Transposed weights: [ic][k][oc], k = kh*9+kw  (2.65 MB)
__device__ float g_wt[CIN * KH * KW * COUT];
// Partial conv sums: [half][b][oc][oh][ow]  (51.4 MB)
__device__ float g_scratch[2 * B_ * COUT * OH * OW];

__device__ __forceinline__ void cp_async16(void* smem, const void* gmem) {
    uint32_t s = (uint32_t)__cvta_generic_to_shared(smem);
    asm volatile("cp.async.cg.shared.global [%0], [%1], 16;\n" :: "r"(s), "l"(gmem));
}
__device__ __forceinline__ void cp_commit() {
    asm volatile("cp.async.commit_group;\n" ::);
}
__device__ __forceinline__ void cp_wait_all() {
    asm volatile("cp.async.wait_group 0;\n" ::);
}

__global__ void transpose_w_kernel(const float* __restrict__ W) {
    int i = blockIdx.x * blockDim.x + threadIdx.x;
    const int total = CIN * KH * KW * COUT;
    if (i >= total) return;
    int ic = i / (KH * KW * COUT);
    int r  = i % (KH * KW * COUT);
    int k  = r / COUT;
    int oc = r % COUT;
    g_wt[i] = W[((size_t)oc * CIN + ic) * (KH * KW) + k];
}

__global__ __launch_bounds__(NTHR_A)
void conv_partial_kernel(const float* __restrict__ x) {
    __shared__ float sx[2][XROWSA * WIN];    // 2 * 960 floats
    __shared__ float sw[2][KH * KW * COUT];  // 2 * 2592 floats

    const int rt   = blockIdx.x;     // 0..6 row tile
    const int half = blockIdx.y;     // 0..1 ic half
    const int b    = blockIdx.z;     // 0..31 batch
    const int oh0  = rt * THA;
    const int ih0  = oh0 * 2;

    const int tid = threadIdx.x;
    const int ocg = tid & 7;          // 8 oc groups of 4
    const int sg  = tid >> 3;         // 16 spatial groups
    const int row = sg >> 2;          // 0..3 output row within tile
    const int cg  = sg & 3;           // col group: ow base = cg*7

    const float* __restrict__ xg =
        x + ((size_t)b * CIN + half * NICH) * (HIN * WIN) + (size_t)ih0 * WIN;
    const float* __restrict__ wg = g_wt + (size_t)(half * NICH) * (KH * KW * COUT);

    float acc[7][4];
    #pragma unroll
    for (int j = 0; j < 7; ++j)
        #pragma unroll
        for (int o = 0; o < 4; ++o) acc[j][o] = 0.f;

    // stage loader: ic tile -> smem buffer via cp.async
    auto load_stage = [&](int buf, int ic) {
        const float4* xs = reinterpret_cast<const float4*>(xg + (size_t)ic * (HIN * WIN));
        float4* dx = reinterpret_cast<float4*>(sx[buf]);
        #pragma unroll
        for (int i = tid; i < XROWSA * WIN / 4; i += NTHR_A)   // 240 -> <=2 per thread
            cp_async16(dx + i, xs + i);
        const float4* ws = reinterpret_cast<const float4*>(wg + (size_t)ic * (KH * KW * COUT));
        float4* dw = reinterpret_cast<float4*>(sw[buf]);
        #pragma unroll
        for (int i = tid; i < KH * KW * COUT / 4; i += NTHR_A) // 648 -> <=6 per thread
            cp_async16(dw + i, ws + i);
    };

    int cur = 0;
    load_stage(0, 0);
    cp_commit();

    for (int ic = 0; ic < NICH; ++ic) {
        cp_wait_all();        // buf[cur] data arrived
        __syncthreads();      // visible to all; all warps done with buf[1-cur] compute
        if (ic + 1 < NICH) {  // overlap next load with this compute
            load_stage(1 - cur, ic + 1);
            cp_commit();
        }

        const float* __restrict__ xb = sx[cur];
        const float* __restrict__ wb = sw[cur];
        #pragma unroll 1
        for (int kh = 0; kh < KH; ++kh) {
            const float* xr = &xb[(2 * row + kh) * WIN + cg * 14];
            const float* wr = &wb[(kh * KW) * COUT + ocg * 4];
            #pragma unroll
            for (int kw = 0; kw < KW; ++kw) {
                float4 wv = *reinterpret_cast<const float4*>(wr + kw * COUT);
                float xv[7];
                #pragma unroll
                for (int j = 0; j < 7; ++j) xv[j] = xr[kw + 2 * j];
                #pragma unroll
                for (int j = 0; j < 7; ++j) {
                    acc[j][0] = fmaf(xv[j], wv.x, acc[j][0]);
                    acc[j][1] = fmaf(xv[j], wv.y, acc[j][1]);
                    acc[j][2] = fmaf(xv[j], wv.z, acc[j][2]);
                    acc[j][3] = fmaf(xv[j], wv.w, acc[j][3]);
                }
            }
        }
        cur ^= 1;
    }

    // write partial sums (no bias) to scratch [half][b][oc][oh][ow]
    float* sc = g_scratch + ((size_t)half * B_ + b) * NPOS;
    const int oh = oh0 + row;
    #pragma unroll
    for (int o = 0; o < 4; ++o) {
        const int oc = ocg * 4 + o;
        float* scr = sc + oc * (OH * OW) + oh * OW + cg * 7;
        #pragma unroll
        for (int j = 0; j < 7; ++j) scr[j] = acc[j][o];
    }
}

__global__ __launch_bounds__(256)
void squash_kernel(const float* __restrict__ bias, float* __restrict__ out) {
    int idx = blockIdx.x * 256 + threadIdx.x;
    if (idx >= B_ * NPOS) return;
    int n  = idx % NPOS;
    int oc = n / (OH * OW);
    float v = g_scratch[idx] + g_scratch[B_ * NPOS + idx] + bias[oc];
    float sq = 8.f * v * v;
    float scale = (sq / (1.f + sq)) * rsqrtf(sq + 1e-8f);
    float sv = v * scale;
    float4 f4 = make_float4(sv, sv, sv, sv);
    float4* o4 = reinterpret_cast<float4*>(out);
    o4[(size_t)idx * 2]     = f4;
    o4[(size_t)idx * 2 + 1] = f4;
}

extern "C" void kernel_launch(void* const* d_in, const int* in_sizes, int n_in,
                              void* d_out, int out_size) {
    const float* x    = (const float*)d_in[0];
    const float* W    = (const float*)d_in[1];
    const float* bias = (const float*)d_in[2];
    float* out = (float*)d_out;

    // 1) transpose weights into [ic][k][oc]
    const int wtotal = CIN * KH * KW * COUT;
    transpose_w_kernel<<<(wtotal + 255) / 256, 256>>>(W);

    // 2) conv partial sums, ic split across 2 block sets (448 blocks, fully resident)
    dim3 gridA(OH / THA / 1, 2, B_);          // (7, 2, 32)
    conv_partial_kernel<<<gridA, NTHR_A>>>(x);

    // 3) combine halves + bias + squash + broadcast T=8
    const int total = B_ * NPOS;
    squash_kernel<<<(total + 255) / 256, 256>>>(bias, out);
}

// round 8
// speedup vs baseline: 1.7004x; 1.7004x over previous
#include <cuda_runtime.h>
#include <cuda_bf16.h>
#include <cstdint>

#define B_     32
#define NPOS   25088
#define NCHUNK 1312     // 32 icb * 41 k16-chunks (koff padded 81->82)

// staged x: [b][icb][ih64][parity2][q32][ic8] bf16; 65536 B per (b,icb)
__device__ __align__(16) unsigned char g_xh[32u * 32u * 65536u];
__device__ __align__(16) unsigned char g_xl[32u * 32u * 65536u];
// packed B fragments: [type hi/lo][chunk][oc32][pack4: halves (k0,k0+1,k0+8,k0+9)] -> 1KB/chunk
__device__ __align__(16) unsigned char g_wb[2u * NCHUNK * 1024u];

// ---------------- x prep: f32 -> bf16 hi/lo, parity-split staged layout ----------------
__global__ void xprep(const float* __restrict__ x) {
    int i = blockIdx.x * 256 + threadIdx.x;          // 2097152 total
    int q = i & 31, r = (i >> 5) & 63, icb = (i >> 11) & 31, b = i >> 16;
    const float* xp = x + (((size_t)b * 256 + icb * 8) * 64 + r) * 64 + 2 * q;
    uint32_t h0[4], h1[4], l0[4], l1[4];
    #pragma unroll
    for (int j = 0; j < 4; ++j) {
        uint32_t ha = 0, hb = 0, la = 0, lb = 0;
        #pragma unroll
        for (int e = 0; e < 2; ++e) {
            float2 v = *reinterpret_cast<const float2*>(xp + (size_t)(2 * j + e) * 4096);
            __nv_bfloat16 hx = __float2bfloat16(v.x);
            __nv_bfloat16 hy = __float2bfloat16(v.y);
            __nv_bfloat16 lx = __float2bfloat16(v.x - __bfloat162float(hx));
            __nv_bfloat16 ly = __float2bfloat16(v.y - __bfloat162float(hy));
            ha |= (uint32_t)__bfloat16_as_ushort(hx) << (e * 16);
            hb |= (uint32_t)__bfloat16_as_ushort(hy) << (e * 16);
            la |= (uint32_t)__bfloat16_as_ushort(lx) << (e * 16);
            lb |= (uint32_t)__bfloat16_as_ushort(ly) << (e * 16);
        }
        h0[j] = ha; h1[j] = hb; l0[j] = la; l1[j] = lb;
    }
    size_t o = ((size_t)(b * 32 + icb) * 64 + r) * 64 + q;   // 16B units; parity1 at +32
    reinterpret_cast<uint4*>(g_xh)[o]      = make_uint4(h0[0], h0[1], h0[2], h0[3]);
    reinterpret_cast<uint4*>(g_xh)[o + 32] = make_uint4(h1[0], h1[1], h1[2], h1[3]);
    reinterpret_cast<uint4*>(g_xl)[o]      = make_uint4(l0[0], l0[1], l0[2], l0[3]);
    reinterpret_cast<uint4*>(g_xl)[o + 32] = make_uint4(l1[0], l1[1], l1[2], l1[3]);
}

// ---------------- W prep: pack B fragments in mma.sync b-register order ----------------
__global__ void wprep(const float* __restrict__ W) {
    int i = blockIdx.x * 256 + threadIdx.x;          // NCHUNK*128 = 167936
    if (i >= NCHUNK * 128) return;
    int p = i & 3, oc = (i >> 2) & 31, c = i >> 7;
    int icb = c / 41, j = c - icb * 41;
    int k0 = 2 * j, k1 = k0 + 1;                     // k1 == 81 -> zero pad
    unsigned short hh[4], ll[4];
    #pragma unroll
    for (int kk = 0; kk < 2; ++kk) {
        int koff = kk ? k1 : k0;
        #pragma unroll
        for (int e = 0; e < 2; ++e) {
            int ic = icb * 8 + 2 * p + e;
            float v = (koff <= 80) ? W[((size_t)oc * 256 + ic) * 81 + koff] : 0.f;
            __nv_bfloat16 h = __float2bfloat16(v);
            __nv_bfloat16 l = __float2bfloat16(v - __bfloat162float(h));
            hh[kk * 2 + e] = __bfloat16_as_ushort(h);
            ll[kk * 2 + e] = __bfloat16_as_ushort(l);
        }
    }
    uint2 ph = make_uint2((uint32_t)hh[0] | ((uint32_t)hh[1] << 16),
                          (uint32_t)hh[2] | ((uint32_t)hh[3] << 16));
    uint2 pl = make_uint2((uint32_t)ll[0] | ((uint32_t)ll[1] << 16),
                          (uint32_t)ll[2] | ((uint32_t)ll[3] << 16));
    size_t off = (size_t)c * 1024 + oc * 32 + p * 8;
    *reinterpret_cast<uint2*>(g_wb + off)                            = ph;
    *reinterpret_cast<uint2*>(g_wb + (size_t)NCHUNK * 1024 + off)    = pl;
}

// ---------------- main: mma.sync implicit GEMM + fused squash epilogue ----------------
__device__ __forceinline__ void mma_bf16(float* c, const uint32_t* a, uint32_t b0, uint32_t b1) {
    asm volatile("mma.sync.aligned.m16n8k16.row.col.f32.bf16.bf16.f32 "
        "{%0,%1,%2,%3}, {%4,%5,%6,%7}, {%8,%9}, {%0,%1,%2,%3};"
        : "+f"(c[0]), "+f"(c[1]), "+f"(c[2]), "+f"(c[3])
        : "r"(a[0]), "r"(a[1]), "r"(a[2]), "r"(a[3]), "r"(b0), "r"(b1));
}

__global__ __launch_bounds__(128, 4)
void conv_mma(const float* __restrict__ bias, float* __restrict__ out) {
    __shared__ int s_i0[NCHUNK], s_i1[NCHUNK];
    __shared__ float s_bias[32];
    const int tid = threadIdx.x, wid = tid >> 5, lane = tid & 31;
    const int ohg = blockIdx.x, b = blockIdx.y;

    for (int c = tid; c < NCHUNK; c += 128) {
        int icb = c / 41, j = c - icb * 41;
        int k0 = 2 * j, k1 = (k0 < 80) ? k0 + 1 : 80;   // pad chunk: reuse 80's addr (B=0)
        int kh0 = k0 / 9, kw0 = k0 - 9 * kh0;
        int kh1 = k1 / 9, kw1 = k1 - 9 * kh1;
        s_i0[c] = icb * 65536 + kh0 * 1024 + (kw0 & 1) * 512 + (kw0 >> 1) * 16;
        s_i1[c] = icb * 65536 + kh1 * 1024 + (kw1 & 1) * 512 + (kw1 >> 1) * 16;
    }
    if (tid < 32) s_bias[tid] = bias[tid];
    __syncthreads();

    const int oh   = ohg * 2 + (wid >> 1);
    const int ow_a = (wid & 1) * 16 + (lane >> 2);
    const int ow_b = ow_a + 8;
    const uint32_t oA = (uint32_t)((ow_a > 27 ? 27 : ow_a) * 16 + (lane & 3) * 4);
    const uint32_t oB = (uint32_t)((ow_b > 27 ? 27 : ow_b) * 16 + (lane & 3) * 4);
    const unsigned char* xh = g_xh + (size_t)b * (32u * 65536u) + (uint32_t)oh * 2048u;
    const unsigned char* xl = g_xl + (size_t)b * (32u * 65536u) + (uint32_t)oh * 2048u;
    const unsigned char* wbh = g_wb + ((lane >> 2) * 32 + (lane & 3) * 8);
    const unsigned char* wbl = wbh + (size_t)NCHUNK * 1024;

    float acc[4][4];
    #pragma unroll
    for (int g = 0; g < 4; ++g)
        #pragma unroll
        for (int q = 0; q < 4; ++q) acc[g][q] = 0.f;

    // prefetch chunk 0
    uint32_t Ah[4], Al[4];
    uint2 Bh[4], Bl[4];
    {
        const int u0 = s_i0[0], u1 = s_i1[0];
        Ah[0] = *(const uint32_t*)(xh + u0 + oA);
        Ah[1] = *(const uint32_t*)(xh + u0 + oB);
        Ah[2] = *(const uint32_t*)(xh + u1 + oA);
        Ah[3] = *(const uint32_t*)(xh + u1 + oB);
        Al[0] = *(const uint32_t*)(xl + u0 + oA);
        Al[1] = *(const uint32_t*)(xl + u0 + oB);
        Al[2] = *(const uint32_t*)(xl + u1 + oA);
        Al[3] = *(const uint32_t*)(xl + u1 + oB);
        #pragma unroll
        for (int g = 0; g < 4; ++g) {
            Bh[g] = *(const uint2*)(wbh + g * 256);
            Bl[g] = *(const uint2*)(wbl + g * 256);
        }
    }

    #pragma unroll 2
    for (int c = 0; c < NCHUNK; ++c) {
        // prefetch next chunk into fresh registers
        uint32_t nAh[4], nAl[4];
        uint2 nBh[4], nBl[4];
        const int cn = (c + 1 < NCHUNK) ? c + 1 : c;
        {
            const int u0 = s_i0[cn], u1 = s_i1[cn];
            nAh[0] = *(const uint32_t*)(xh + u0 + oA);
            nAh[1] = *(const uint32_t*)(xh + u0 + oB);
            nAh[2] = *(const uint32_t*)(xh + u1 + oA);
            nAh[3] = *(const uint32_t*)(xh + u1 + oB);
            nAl[0] = *(const uint32_t*)(xl + u0 + oA);
            nAl[1] = *(const uint32_t*)(xl + u0 + oB);
            nAl[2] = *(const uint32_t*)(xl + u1 + oA);
            nAl[3] = *(const uint32_t*)(xl + u1 + oB);
            const unsigned char* wh = wbh + (size_t)cn * 1024;
            const unsigned char* wl = wbl + (size_t)cn * 1024;
            #pragma unroll
            for (int g = 0; g < 4; ++g) {
                nBh[g] = *(const uint2*)(wh + g * 256);
                nBl[g] = *(const uint2*)(wl + g * 256);
            }
        }
        // compute current chunk: 3-product hi/lo split
        #pragma unroll
        for (int g = 0; g < 4; ++g) {
            mma_bf16(acc[g], Ah, Bh[g].x, Bh[g].y);   // xh * wh
            mma_bf16(acc[g], Al, Bh[g].x, Bh[g].y);   // xl * wh
            mma_bf16(acc[g], Ah, Bl[g].x, Bl[g].y);   // xh * wl
        }
        #pragma unroll
        for (int k = 0; k < 4; ++k) { Ah[k] = nAh[k]; Al[k] = nAl[k]; Bh[k] = nBh[k]; Bl[k] = nBl[k]; }
    }

    // epilogue: bias + squash + T=8 broadcast
    float4* o4 = reinterpret_cast<float4*>(out);
    const size_t ob = (size_t)b * NPOS;
    #pragma unroll
    for (int g = 0; g < 4; ++g) {
        #pragma unroll
        for (int q = 0; q < 4; ++q) {
            const int ow = (q < 2) ? ow_a : ow_b;
            if (ow > 27) continue;
            const int oc = g * 8 + (lane & 3) * 2 + (q & 1);
            float v = acc[g][q] + s_bias[oc];
            float sq = 8.f * v * v;
            float sv = v * (sq / (1.f + sq)) * rsqrtf(sq + 1e-8f);
            float4 f4 = make_float4(sv, sv, sv, sv);
            size_t idx = (ob + (size_t)(oc * 784 + oh * 28 + ow)) * 2;
            o4[idx]     = f4;
            o4[idx + 1] = f4;
        }
    }
}

extern "C" void kernel_launch(void* const* d_in, const int* in_sizes, int n_in,
                              void* d_out, int out_size) {
    const float* x    = (const float*)d_in[0];
    const float* W    = (const float*)d_in[1];
    const float* bias = (const float*)d_in[2];
    float* out = (float*)d_out;

    xprep<<<2097152 / 256, 256>>>(x);
    wprep<<<(NCHUNK * 128 + 255) / 256, 256>>>(W);
    dim3 grid(14, B_);                    // 448 CTAs, 128 threads
    conv_mma<<<grid, 128>>>(bias, out);
}

// round 9
// speedup vs baseline: 1.7194x; 1.0112x over previous
#include <cuda_runtime.h>
#include <cuda_bf16.h>
#include <cstdint>

#define B_     32
#define NPOS   25088
#define NCHUNK 1312     // 32 icb * 41 k16-chunks (koff padded 81->82)

// staged x: [b][icb][ih64][parity2][q32][p4][hi4B|lo4B]  -> 131072 B per (b,icb)
__device__ __align__(16) unsigned char g_x[32u * 32u * 131072u];
// packed B fragments: [chunk][g4][col8][p4][hi8B|lo8B] -> 2048 B per chunk
__device__ __align__(16) unsigned char g_wb[(size_t)NCHUNK * 2048u];

// ---------------- x prep: f32 -> bf16 hi/lo interleaved, parity-split ----------------
__global__ void xprep(const float* __restrict__ x) {
    int i = blockIdx.x * 256 + threadIdx.x;          // 2097152 total
    int q = i & 31, r = (i >> 5) & 63, icb = (i >> 11) & 31, b = i >> 16;
    const float* xp = x + (((size_t)b * 256 + icb * 8) * 64 + r) * 64 + 2 * q;
    uint32_t h0[4], h1[4], l0[4], l1[4];
    #pragma unroll
    for (int j = 0; j < 4; ++j) {
        uint32_t ha = 0, hb = 0, la = 0, lb = 0;
        #pragma unroll
        for (int e = 0; e < 2; ++e) {
            float2 v = *reinterpret_cast<const float2*>(xp + (size_t)(2 * j + e) * 4096);
            __nv_bfloat16 hx = __float2bfloat16(v.x);
            __nv_bfloat16 hy = __float2bfloat16(v.y);
            __nv_bfloat16 lx = __float2bfloat16(v.x - __bfloat162float(hx));
            __nv_bfloat16 ly = __float2bfloat16(v.y - __bfloat162float(hy));
            ha |= (uint32_t)__bfloat16_as_ushort(hx) << (e * 16);
            hb |= (uint32_t)__bfloat16_as_ushort(hy) << (e * 16);
            la |= (uint32_t)__bfloat16_as_ushort(lx) << (e * 16);
            lb |= (uint32_t)__bfloat16_as_ushort(ly) << (e * 16);
        }
        h0[j] = ha; h1[j] = hb; l0[j] = la; l1[j] = lb;
    }
    size_t ub = (size_t)(b * 32 + icb) * 131072u + (uint32_t)r * 2048u + (uint32_t)q * 32u;
    *reinterpret_cast<uint4*>(g_x + ub)          = make_uint4(h0[0], l0[0], h0[1], l0[1]);
    *reinterpret_cast<uint4*>(g_x + ub + 16)     = make_uint4(h0[2], l0[2], h0[3], l0[3]);
    *reinterpret_cast<uint4*>(g_x + ub + 1024)   = make_uint4(h1[0], l1[0], h1[1], l1[1]);
    *reinterpret_cast<uint4*>(g_x + ub + 1040)   = make_uint4(h1[2], l1[2], h1[3], l1[3]);
}

// ---------------- W prep: B fragments, hi/lo interleaved per lane (16B) ----------------
__global__ void wprep(const float* __restrict__ W) {
    int i = blockIdx.x * 256 + threadIdx.x;          // NCHUNK*128 = 167936
    if (i >= NCHUNK * 128) return;
    int p = i & 3, oc = (i >> 2) & 31, c = i >> 7;
    int icb = c / 41, j = c - icb * 41;
    int k0 = 2 * j, k1 = k0 + 1;                     // k1 == 81 -> zero pad
    unsigned short hh[4], ll[4];
    #pragma unroll
    for (int kk = 0; kk < 2; ++kk) {
        int koff = kk ? k1 : k0;
        #pragma unroll
        for (int e = 0; e < 2; ++e) {
            int ic = icb * 8 + 2 * p + e;
            float v = (koff <= 80) ? W[((size_t)oc * 256 + ic) * 81 + koff] : 0.f;
            __nv_bfloat16 h = __float2bfloat16(v);
            __nv_bfloat16 l = __float2bfloat16(v - __bfloat162float(h));
            hh[kk * 2 + e] = __bfloat16_as_ushort(h);
            ll[kk * 2 + e] = __bfloat16_as_ushort(l);
        }
    }
    uint4 pk = make_uint4((uint32_t)hh[0] | ((uint32_t)hh[1] << 16),
                          (uint32_t)hh[2] | ((uint32_t)hh[3] << 16),
                          (uint32_t)ll[0] | ((uint32_t)ll[1] << 16),
                          (uint32_t)ll[2] | ((uint32_t)ll[3] << 16));
    size_t off = (size_t)c * 2048 + (oc >> 3) * 512 + (oc & 7) * 64 + p * 16;
    *reinterpret_cast<uint4*>(g_wb + off) = pk;
}

// ---------------- main: mma.sync implicit GEMM + fused squash epilogue ----------------
__device__ __forceinline__ void mma_bf16(float* c, const uint32_t* a, uint32_t b0, uint32_t b1) {
    asm volatile("mma.sync.aligned.m16n8k16.row.col.f32.bf16.bf16.f32 "
        "{%0,%1,%2,%3}, {%4,%5,%6,%7}, {%8,%9}, {%0,%1,%2,%3};"
        : "+f"(c[0]), "+f"(c[1]), "+f"(c[2]), "+f"(c[3])
        : "r"(a[0]), "r"(a[1]), "r"(a[2]), "r"(a[3]), "r"(b0), "r"(b1));
}

__global__ __launch_bounds__(128, 4)
void conv_mma(const float* __restrict__ bias, float* __restrict__ out) {
    __shared__ int s_i0[NCHUNK], s_i1[NCHUNK];
    __shared__ float s_bias[32];
    const int tid = threadIdx.x, wid = tid >> 5, lane = tid & 31;

    for (int c = tid; c < NCHUNK; c += 128) {
        int icb = c / 41, j = c - icb * 41;
        int k0 = 2 * j, k1 = (k0 < 80) ? k0 + 1 : 80;   // pad chunk reuses 80's addr (B lo half = 0)
        int kh0 = k0 / 9, kw0 = k0 - 9 * kh0;
        int kh1 = k1 / 9, kw1 = k1 - 9 * kh1;
        s_i0[c] = icb * 131072 + kh0 * 2048 + (kw0 & 1) * 1024 + (kw0 >> 1) * 32;
        s_i1[c] = icb * 131072 + kh1 * 2048 + (kw1 & 1) * 1024 + (kw1 >> 1) * 32;
    }
    if (tid < 32) s_bias[tid] = bias[tid];
    __syncthreads();

    // warp-tile: 1568 total = 32 b x 49 m16 tiles; pos = tile*16 + row, pos -> (oh,ow)
    const int gidx = blockIdx.x * 4 + wid;
    const int b    = gidx / 49;
    const int tile = gidx - b * 49;
    const int pos_a = tile * 16 + (lane >> 2);
    const int pos_b = pos_a + 8;
    const int oh_a = pos_a / 28, ow_a = pos_a - 28 * oh_a;
    const int oh_b = pos_b / 28, ow_b = pos_b - 28 * oh_b;
    const uint32_t oA = (uint32_t)(oh_a * 4096 + ow_a * 32 + (lane & 3) * 8);
    const uint32_t oB = (uint32_t)(oh_b * 4096 + ow_b * 32 + (lane & 3) * 8);
    const unsigned char* xb  = g_x  + (size_t)b * (32u * 131072u);
    const unsigned char* wbp = g_wb + ((lane >> 2) * 64 + (lane & 3) * 16);

    float acc[4][4];
    #pragma unroll
    for (int g = 0; g < 4; ++g)
        #pragma unroll
        for (int q = 0; q < 4; ++q) acc[g][q] = 0.f;

    // prefetch chunk 0
    uint2 A[4];                  // .x = hi, .y = lo
    uint4 Bv[4];                 // .x,.y = hi frag; .z,.w = lo frag
    {
        const int u0 = s_i0[0], u1 = s_i1[0];
        A[0] = *(const uint2*)(xb + u0 + oA);
        A[1] = *(const uint2*)(xb + u0 + oB);
        A[2] = *(const uint2*)(xb + u1 + oA);
        A[3] = *(const uint2*)(xb + u1 + oB);
        #pragma unroll
        for (int g = 0; g < 4; ++g) Bv[g] = *(const uint4*)(wbp + g * 512);
    }

    #pragma unroll 2
    for (int c = 0; c < NCHUNK; ++c) {
        uint2 nA[4];
        uint4 nB[4];
        const int cn = (c + 1 < NCHUNK) ? c + 1 : c;
        {
            const int u0 = s_i0[cn], u1 = s_i1[cn];
            nA[0] = *(const uint2*)(xb + u0 + oA);
            nA[1] = *(const uint2*)(xb + u0 + oB);
            nA[2] = *(const uint2*)(xb + u1 + oA);
            nA[3] = *(const uint2*)(xb + u1 + oB);
            const unsigned char* wp = wbp + (size_t)cn * 2048;
            #pragma unroll
            for (int g = 0; g < 4; ++g) nB[g] = *(const uint4*)(wp + g * 512);
        }
        uint32_t Ah[4] = {A[0].x, A[1].x, A[2].x, A[3].x};
        uint32_t Al[4] = {A[0].y, A[1].y, A[2].y, A[3].y};
        #pragma unroll
        for (int g = 0; g < 4; ++g) {
            mma_bf16(acc[g], Ah, Bv[g].x, Bv[g].y);   // xh * wh
            mma_bf16(acc[g], Al, Bv[g].x, Bv[g].y);   // xl * wh
            mma_bf16(acc[g], Ah, Bv[g].z, Bv[g].w);   // xh * wl
        }
        #pragma unroll
        for (int k = 0; k < 4; ++k) { A[k] = nA[k]; Bv[k] = nB[k]; }
    }

    // epilogue: bias + squash + T=8 broadcast (all positions valid)
    float4* o4 = reinterpret_cast<float4*>(out);
    const size_t ob = (size_t)b * NPOS;
    #pragma unroll
    for (int g = 0; g < 4; ++g) {
        #pragma unroll
        for (int q = 0; q < 4; ++q) {
            const int pos = (q < 2) ? pos_a : pos_b;
            const int oc  = g * 8 + (lane & 3) * 2 + (q & 1);
            float v = acc[g][q] + s_bias[oc];
            float sq = 8.f * v * v;
            float sv = v * (sq / (1.f + sq)) * rsqrtf(sq + 1e-8f);
            float4 f4 = make_float4(sv, sv, sv, sv);
            size_t idx = (ob + (size_t)(oc * 784 + pos)) * 2;
            o4[idx]     = f4;
            o4[idx + 1] = f4;
        }
    }
}

extern "C" void kernel_launch(void* const* d_in, const int* in_sizes, int n_in,
                              void* d_out, int out_size) {
    const float* x    = (const float*)d_in[0];
    const float* W    = (const float*)d_in[1];
    const float* bias = (const float*)d_in[2];
    float* out = (float*)d_out;

    xprep<<<2097152 / 256, 256>>>(x);
    wprep<<<(NCHUNK * 128 + 255) / 256, 256>>>(W);
    conv_mma<<<392, 128>>>(bias, out);   // 392 CTAs = 1568 warp-tiles / 4
}